// round 1
// baseline (speedup 1.0000x reference)
#include <cuda_runtime.h>

#define N_NODES 100000
#define N_EDGES 1600000
#define D 128

// Scratch (no allocations allowed): per-node interleaved [y2(128) | y34(128)]
__device__ float g_y[(size_t)N_NODES * 256];
// Scatter accumulators, same interleaved layout
__device__ float g_s[(size_t)N_NODES * 256];
// Combined weights [384][128]: rows 0-127 = W1, 128-255 = 2*W2, 256-383 = 2*(W3+W4)
__device__ float g_Wc[384 * 128];
__device__ float g_bc[384];

__global__ void prep_kernel(const float* __restrict__ W1, const float* __restrict__ b1,
                            const float* __restrict__ W2, const float* __restrict__ b2,
                            const float* __restrict__ W3, const float* __restrict__ b3,
                            const float* __restrict__ W4, const float* __restrict__ b4) {
    int idx = blockIdx.x * blockDim.x + threadIdx.x;
    if (idx < 384 * 128) {
        int r = idx >> 7, c = idx & 127;
        float v;
        if (r < 128)      v = W1[idx];
        else if (r < 256) v = 2.f * W2[(r - 128) * 128 + c];
        else              v = 2.f * (W3[(r - 256) * 128 + c] + W4[(r - 256) * 128 + c]);
        g_Wc[idx] = v;
    }
    if (idx < 384) {
        float v;
        if (idx < 128)      v = b1[idx];
        else if (idx < 256) v = 2.f * b2[idx - 128];
        else                v = 2.f * (b3[idx - 256] + b4[idx - 256]);
        g_bc[idx] = v;
    }
}

__global__ void zero_kernel() {
    size_t i = (size_t)blockIdx.x * blockDim.x + threadIdx.x;
    if (i < (size_t)N_NODES * 64)
        ((float4*)g_s)[i] = make_float4(0.f, 0.f, 0.f, 0.f);
}

#define XS_LD 132
#define WS_LD 132

// Fused GEMM: out[m][0:384] = x[m] @ Wc^T + bc.
// n in [0,128)   -> d_out (x1 path)
// n in [128,384) -> g_y   (doubled y2 / y34, interleaved per node)
__global__ void __launch_bounds__(256, 2) gemm_kernel(const float* __restrict__ x,
                                                      float* __restrict__ out) {
    extern __shared__ float sh[];
    float* xs = sh;               // [64][XS_LD]
    float* ws = sh + 64 * XS_LD;  // [128][WS_LD], transposed: ws[k][n]

    const int m0 = blockIdx.x * 64;
    const int n0 = blockIdx.y * 128;
    const int t  = threadIdx.x;

    // Load x tile (64 x 128) as float4, zero-pad tail rows
    #pragma unroll
    for (int i = t; i < 64 * 32; i += 256) {
        int row = i >> 5, c4 = i & 31;
        int gm = m0 + row;
        float4 v = (gm < N_NODES) ? ((const float4*)x)[(size_t)gm * 32 + c4]
                                  : make_float4(0.f, 0.f, 0.f, 0.f);
        *(float4*)(xs + row * XS_LD + c4 * 4) = v;
    }
    // Load W tile transposed: g_Wc[(n0+n)][k] -> ws[k][n]
    for (int i = t; i < 128 * 128; i += 256) {
        int n = i >> 7, k = i & 127;
        ws[k * WS_LD + n] = g_Wc[(n0 + n) * 128 + k];
    }
    __syncthreads();

    const int tx = t & 15, ty = t >> 4;
    const int mb = ty * 4, nb = tx * 8;
    float acc[4][8];
    #pragma unroll
    for (int i = 0; i < 4; i++)
        #pragma unroll
        for (int j = 0; j < 8; j++) acc[i][j] = 0.f;

    #pragma unroll 4
    for (int k = 0; k < 128; k++) {
        float a0 = xs[(mb + 0) * XS_LD + k];
        float a1 = xs[(mb + 1) * XS_LD + k];
        float a2 = xs[(mb + 2) * XS_LD + k];
        float a3 = xs[(mb + 3) * XS_LD + k];
        const float4* wp = (const float4*)(ws + k * WS_LD + nb);
        float4 w0 = wp[0], w1 = wp[1];
        float bb[8] = {w0.x, w0.y, w0.z, w0.w, w1.x, w1.y, w1.z, w1.w};
        #pragma unroll
        for (int j = 0; j < 8; j++) {
            acc[0][j] = fmaf(a0, bb[j], acc[0][j]);
            acc[1][j] = fmaf(a1, bb[j], acc[1][j]);
            acc[2][j] = fmaf(a2, bb[j], acc[2][j]);
            acc[3][j] = fmaf(a3, bb[j], acc[3][j]);
        }
    }

    float bias[8];
    #pragma unroll
    for (int j = 0; j < 8; j++) bias[j] = g_bc[n0 + nb + j];

    #pragma unroll
    for (int i = 0; i < 4; i++) {
        int m = m0 + mb + i;
        if (m >= N_NODES) continue;
        float4 v0 = make_float4(acc[i][0] + bias[0], acc[i][1] + bias[1],
                                acc[i][2] + bias[2], acc[i][3] + bias[3]);
        float4 v1 = make_float4(acc[i][4] + bias[4], acc[i][5] + bias[5],
                                acc[i][6] + bias[6], acc[i][7] + bias[7]);
        if (n0 == 0) {
            float4* o = (float4*)(out + (size_t)m * 128 + nb);
            o[0] = v0; o[1] = v1;
        } else {
            float4* o = (float4*)(g_y + (size_t)m * 256 + (n0 - 128) + nb);
            o[0] = v0; o[1] = v1;
        }
    }
}

// One warp per edge: gather 256 floats of y[src], vector-reduce into s[dst].
__global__ void scatter_kernel(const int* __restrict__ edge) {
    int gid = blockIdx.x * blockDim.x + threadIdx.x;
    int e = gid >> 5;
    int lane = gid & 31;
    if (e >= N_EDGES) return;
    int src = __ldg(edge + e);            // edge_idx[0][e]
    int dst = __ldg(edge + N_EDGES + e);  // edge_idx[1][e]
    const float4* yrow = (const float4*)(g_y + (size_t)src * 256);
    float4* srow = (float4*)(g_s + (size_t)dst * 256);
    float4 v0 = __ldg(yrow + lane);
    float4 v1 = __ldg(yrow + lane + 32);
    asm volatile("red.global.add.v4.f32 [%0], {%1,%2,%3,%4};"
                 :: "l"(srow + lane), "f"(v0.x), "f"(v0.y), "f"(v0.z), "f"(v0.w)
                 : "memory");
    asm volatile("red.global.add.v4.f32 [%0], {%1,%2,%3,%4};"
                 :: "l"(srow + lane + 32), "f"(v1.x), "f"(v1.y), "f"(v1.z), "f"(v1.w)
                 : "memory");
}

// out = sigmoid(s34) * s2 + x1   (x1 already in d_out)
__global__ void final_kernel(float* __restrict__ out) {
    int i = blockIdx.x * blockDim.x + threadIdx.x;
    if (i >= N_NODES * 32) return;
    int node = i >> 5, c4 = i & 31;
    float4 s2  = ((const float4*)g_s)[(size_t)node * 64 + c4];
    float4 s34 = ((const float4*)g_s)[(size_t)node * 64 + 32 + c4];
    float4 x1  = ((float4*)out)[i];
    float4 r;
    r.x = fmaf(s2.x, __frcp_rn(1.f + __expf(-s34.x)), x1.x);
    r.y = fmaf(s2.y, __frcp_rn(1.f + __expf(-s34.y)), x1.y);
    r.z = fmaf(s2.z, __frcp_rn(1.f + __expf(-s34.z)), x1.z);
    r.w = fmaf(s2.w, __frcp_rn(1.f + __expf(-s34.w)), x1.w);
    ((float4*)out)[i] = r;
}

extern "C" void kernel_launch(void* const* d_in, const int* in_sizes, int n_in,
                              void* d_out, int out_size) {
    const float* x  = (const float*)d_in[0];
    const int* edge = (const int*)d_in[1];
    const float* W1 = (const float*)d_in[2];
    const float* b1 = (const float*)d_in[3];
    const float* W2 = (const float*)d_in[4];
    const float* b2 = (const float*)d_in[5];
    const float* W3 = (const float*)d_in[6];
    const float* b3 = (const float*)d_in[7];
    const float* W4 = (const float*)d_in[8];
    const float* b4 = (const float*)d_in[9];
    float* out = (float*)d_out;

    int smem = (64 * XS_LD + 128 * WS_LD) * (int)sizeof(float);
    cudaFuncSetAttribute(gemm_kernel, cudaFuncAttributeMaxDynamicSharedMemorySize, smem);

    prep_kernel<<<(384 * 128 + 255) / 256, 256>>>(W1, b1, W2, b2, W3, b3, W4, b4);
    zero_kernel<<<(N_NODES * 64 + 255) / 256, 256>>>();
    dim3 grid((N_NODES + 63) / 64, 3);
    gemm_kernel<<<grid, 256, smem>>>(x, out);
    scatter_kernel<<<(N_EDGES * 32 + 255) / 256, 256>>>(edge);
    final_kernel<<<(N_NODES * 32 + 255) / 256, 256>>>(out);
}

// round 3
// speedup vs baseline: 1.5010x; 1.5010x over previous
#include <cuda_runtime.h>
#include <cuda_bf16.h>
#include <cstdint>

#define N_NODES 100000
#define N_EDGES 1600000

// ---------------- scratch (static, no allocs) ----------------
__device__ float g_y2 [(size_t)N_NODES * 128];
__device__ float g_y34[(size_t)N_NODES * 128];
__device__ float g_s2 [(size_t)N_NODES * 128];
__device__ float g_s34[(size_t)N_NODES * 128];
// Combined weights split to bf16 hi/lo. Rows 0-127 = W1, 128-255 = 2*W2, 256-383 = 2*(W3+W4)
__device__ __nv_bfloat16 g_Wh[384 * 128];
__device__ __nv_bfloat16 g_Wl[384 * 128];
__device__ float g_bc[384];

__device__ __forceinline__ uint32_t smem_u32(const void* p) {
    uint32_t a;
    asm("{ .reg .u64 t; cvta.to.shared.u64 t, %1; cvt.u32.u64 %0, t; }" : "=r"(a) : "l"(p));
    return a;
}
__device__ __forceinline__ void ldm4(uint32_t* r, uint32_t addr) {
    asm volatile("ldmatrix.sync.aligned.m8n8.x4.shared.b16 {%0,%1,%2,%3}, [%4];"
                 : "=r"(r[0]), "=r"(r[1]), "=r"(r[2]), "=r"(r[3]) : "r"(addr));
}
__device__ __forceinline__ void mma_bf16(float* d, const uint32_t* a, const uint32_t* b) {
    asm volatile(
        "mma.sync.aligned.m16n8k16.row.col.f32.bf16.bf16.f32 "
        "{%0,%1,%2,%3}, {%4,%5,%6,%7}, {%8,%9}, {%0,%1,%2,%3};"
        : "+f"(d[0]), "+f"(d[1]), "+f"(d[2]), "+f"(d[3])
        : "r"(a[0]), "r"(a[1]), "r"(a[2]), "r"(a[3]), "r"(b[0]), "r"(b[1]));
}

// ---------------- prep: build combined W, split bf16 hi/lo ----------------
__global__ void prep_kernel(const float* __restrict__ W1, const float* __restrict__ b1,
                            const float* __restrict__ W2, const float* __restrict__ b2,
                            const float* __restrict__ W3, const float* __restrict__ b3,
                            const float* __restrict__ W4, const float* __restrict__ b4) {
    int idx = blockIdx.x * blockDim.x + threadIdx.x;
    if (idx < 384 * 128) {
        int r = idx >> 7, c = idx & 127;
        float v;
        if (r < 128)      v = W1[idx];
        else if (r < 256) v = 2.f * W2[(r - 128) * 128 + c];
        else              v = 2.f * (W3[(r - 256) * 128 + c] + W4[(r - 256) * 128 + c]);
        __nv_bfloat16 h = __float2bfloat16(v);
        __nv_bfloat16 l = __float2bfloat16(v - __bfloat162float(h));
        g_Wh[idx] = h;
        g_Wl[idx] = l;
    }
    if (idx < 384) {
        float v;
        if (idx < 128)      v = b1[idx];
        else if (idx < 256) v = 2.f * b2[idx - 128];
        else                v = 2.f * (b3[idx - 256] + b4[idx - 256]);
        g_bc[idx] = v;
    }
}

// ---------------- HMMA (mma.sync) bf16x3 GEMM ----------------
// smem tiles (bytes): rows padded to 272B (136 bf16) -> stride ≡ 4 mod 32 words,
// conflict-free ldmatrix. A=x[m][k], B=Wc[n][k] (row.col mma wants exactly this).
#define PITCH_B 272
#define SA_H 0
#define SA_L 34816
#define SB_H 69632
#define SB_L 104448
#define SM_TOT 139264

__global__ void __launch_bounds__(256, 1) gemm_kernel(const float* __restrict__ x,
                                                      float* __restrict__ out) {
    extern __shared__ char smem[];
    const uint32_t sb = smem_u32(smem);
    const int tid = threadIdx.x, lane = tid & 31, wid = tid >> 5;
    const int m0 = blockIdx.x * 128;
    const int wm = wid >> 1, wn = wid & 1;  // 4 x 2 warp grid, warp tile 32(M) x 64(N)

    // Load + split x tile -> A_hi/A_lo
    for (int i = tid; i < 128 * 64; i += 256) {
        int r = i >> 6, p = i & 63;     // row, fp32-pair (k = 2p)
        int m = m0 + r;
        float v0 = 0.f, v1 = 0.f;
        if (m < N_NODES) {
            float2 f = ((const float2*)x)[(size_t)m * 64 + p];
            v0 = f.x; v1 = f.y;
        }
        __nv_bfloat16 h0 = __float2bfloat16(v0), h1 = __float2bfloat16(v1);
        __nv_bfloat16 l0 = __float2bfloat16(v0 - __bfloat162float(h0));
        __nv_bfloat16 l1 = __float2bfloat16(v1 - __bfloat162float(h1));
        uint32_t hp = ((uint32_t)__bfloat16_as_ushort(h1) << 16) | __bfloat16_as_ushort(h0);
        uint32_t lp = ((uint32_t)__bfloat16_as_ushort(l1) << 16) | __bfloat16_as_ushort(l0);
        int off = r * PITCH_B + p * 4;
        *(uint32_t*)(smem + SA_H + off) = hp;
        *(uint32_t*)(smem + SA_L + off) = lp;
    }

    // Per-thread ldmatrix offsets (bytes) within a tile.
    // A x4: groups of 8 lanes -> (m0-7,k0-7)(m8-15,k0-7)(m0-7,k8-15)(m8-15,k8-15)
    const int aOff = ((lane & 7) + ((lane >> 3) & 1) * 8) * PITCH_B + (lane >> 4) * 16;
    // B x4: (n0-7,k0-7)(n0-7,k8-15)(n8-15,k0-7)(n8-15,k8-15)
    const int bOff = ((lane & 7) + ((lane >> 4) & 1) * 8) * PITCH_B + ((lane >> 3) & 1) * 16;

    const int tq = lane >> 2, tr = lane & 3;

    for (int nt = 0; nt < 3; nt++) {
        __syncthreads();  // A ready (nt=0) / previous B reads done (nt>0)
        // Load W n-tile hi/lo
        for (int i = tid; i < 128 * 64; i += 256) {
            int n = i >> 6, p = i & 63;
            uint32_t hp = *(const uint32_t*)(g_Wh + ((size_t)(nt * 128 + n) * 128 + p * 2));
            uint32_t lp = *(const uint32_t*)(g_Wl + ((size_t)(nt * 128 + n) * 128 + p * 2));
            int off = n * PITCH_B + p * 4;
            *(uint32_t*)(smem + SB_H + off) = hp;
            *(uint32_t*)(smem + SB_L + off) = lp;
        }
        __syncthreads();

        float acc[2][8][4];
        #pragma unroll
        for (int mt = 0; mt < 2; mt++)
            #pragma unroll
            for (int nb = 0; nb < 8; nb++)
                #pragma unroll
                for (int j = 0; j < 4; j++) acc[mt][nb][j] = 0.f;

        #pragma unroll
        for (int ks = 0; ks < 8; ks++) {
            const int k0b = ks * 32;  // 16 bf16 = 32 bytes
            uint32_t Ah[2][4], Al[2][4];
            #pragma unroll
            for (int mt = 0; mt < 2; mt++) {
                int tb = (wm * 32 + mt * 16) * PITCH_B + k0b;
                ldm4(Ah[mt], sb + SA_H + tb + aOff);
                ldm4(Al[mt], sb + SA_L + tb + aOff);
            }
            uint32_t Bh[16], Bl[16];
            #pragma unroll
            for (int q = 0; q < 4; q++) {
                int tb = (wn * 64 + q * 16) * PITCH_B + k0b;
                ldm4(Bh + q * 4, sb + SB_H + tb + bOff);
                ldm4(Bl + q * 4, sb + SB_L + tb + bOff);
            }
            #pragma unroll
            for (int mt = 0; mt < 2; mt++)
                #pragma unroll
                for (int nb = 0; nb < 8; nb++) {
                    mma_bf16(acc[mt][nb], Ah[mt], Bh + nb * 2);
                    mma_bf16(acc[mt][nb], Ah[mt], Bl + nb * 2);
                    mma_bf16(acc[mt][nb], Al[mt], Bh + nb * 2);
                }
        }

        // Epilogue: nt0 -> out, nt1 -> g_y2, nt2 -> g_y34 (bias folded in)
        float* base = (nt == 0) ? out : (nt == 1 ? g_y2 : g_y34);
        #pragma unroll
        for (int nb = 0; nb < 8; nb++) {
            int c = wn * 64 + nb * 8 + tr * 2;
            float bx = __ldg(g_bc + nt * 128 + c);
            float by = __ldg(g_bc + nt * 128 + c + 1);
            #pragma unroll
            for (int mt = 0; mt < 2; mt++) {
                int m = m0 + wm * 32 + mt * 16 + tq;
                if (m < N_NODES) {
                    float2 v = make_float2(acc[mt][nb][0] + bx, acc[mt][nb][1] + by);
                    *(float2*)(base + (size_t)m * 128 + c) = v;
                }
                if (m + 8 < N_NODES) {
                    float2 v = make_float2(acc[mt][nb][2] + bx, acc[mt][nb][3] + by);
                    *(float2*)(base + (size_t)(m + 8) * 128 + c) = v;
                }
            }
        }
    }
}

// ---------------- zero + scatter (split by feature half for L2 residency) ----------------
__global__ void zero_s2_kernel() {
    size_t i = (size_t)blockIdx.x * blockDim.x + threadIdx.x;
    if (i < (size_t)N_NODES * 32) ((float4*)g_s2)[i] = make_float4(0.f, 0.f, 0.f, 0.f);
}
__global__ void zero_s34_kernel() {
    size_t i = (size_t)blockIdx.x * blockDim.x + threadIdx.x;
    if (i < (size_t)N_NODES * 32) ((float4*)g_s34)[i] = make_float4(0.f, 0.f, 0.f, 0.f);
}

__device__ __forceinline__ void scatter_half(const int* __restrict__ edge,
                                             const float* __restrict__ y,
                                             float* __restrict__ s) {
    int gid = blockIdx.x * blockDim.x + threadIdx.x;
    int e = gid >> 5, lane = gid & 31;
    if (e >= N_EDGES) return;
    int src = __ldg(edge + e);
    int dst = __ldg(edge + N_EDGES + e);
    float4 v = __ldg((const float4*)(y + (size_t)src * 128) + lane);
    float4* sp = (float4*)(s + (size_t)dst * 128) + lane;
    asm volatile("red.global.add.v4.f32 [%0], {%1,%2,%3,%4};"
                 :: "l"(sp), "f"(v.x), "f"(v.y), "f"(v.z), "f"(v.w) : "memory");
}
__global__ void scatter_a_kernel(const int* __restrict__ edge) { scatter_half(edge, g_y2, g_s2); }
__global__ void scatter_b_kernel(const int* __restrict__ edge) { scatter_half(edge, g_y34, g_s34); }

// ---------------- final: out = sigmoid(s34)*s2 + x1 ----------------
__global__ void final_kernel(float* __restrict__ out) {
    int i = blockIdx.x * blockDim.x + threadIdx.x;
    if (i >= N_NODES * 32) return;
    float4 s2  = ((const float4*)g_s2)[i];
    float4 s34 = ((const float4*)g_s34)[i];
    float4 x1  = ((float4*)out)[i];
    float4 r;
    r.x = fmaf(s2.x, __frcp_rn(1.f + __expf(-s34.x)), x1.x);
    r.y = fmaf(s2.y, __frcp_rn(1.f + __expf(-s34.y)), x1.y);
    r.z = fmaf(s2.z, __frcp_rn(1.f + __expf(-s34.z)), x1.z);
    r.w = fmaf(s2.w, __frcp_rn(1.f + __expf(-s34.w)), x1.w);
    ((float4*)out)[i] = r;
}

extern "C" void kernel_launch(void* const* d_in, const int* in_sizes, int n_in,
                              void* d_out, int out_size) {
    const float* x  = (const float*)d_in[0];
    const int* edge = (const int*)d_in[1];
    const float* W1 = (const float*)d_in[2];
    const float* b1 = (const float*)d_in[3];
    const float* W2 = (const float*)d_in[4];
    const float* b2 = (const float*)d_in[5];
    const float* W3 = (const float*)d_in[6];
    const float* b3 = (const float*)d_in[7];
    const float* W4 = (const float*)d_in[8];
    const float* b4 = (const float*)d_in[9];
    float* out = (float*)d_out;

    cudaFuncSetAttribute(gemm_kernel, cudaFuncAttributeMaxDynamicSharedMemorySize, SM_TOT);

    prep_kernel<<<(384 * 128 + 255) / 256, 256>>>(W1, b1, W2, b2, W3, b3, W4, b4);
    gemm_kernel<<<(N_NODES + 127) / 128, 256, SM_TOT>>>(x, out);
    zero_s2_kernel<<<(N_NODES * 32 + 255) / 256, 256>>>();
    scatter_a_kernel<<<(N_EDGES * 32 + 255) / 256, 256>>>(edge);
    zero_s34_kernel<<<(N_NODES * 32 + 255) / 256, 256>>>();
    scatter_b_kernel<<<(N_EDGES * 32 + 255) / 256, 256>>>(edge);
    final_kernel<<<(N_NODES * 32 + 255) / 256, 256>>>(out);
}

// round 4
// speedup vs baseline: 2.5578x; 1.7041x over previous
#include <cuda_runtime.h>
#include <cuda_bf16.h>
#include <cstdint>

#define N_NODES 100000
#define N_EDGES 1600000
#define NBLK ((N_NODES + 255) / 256)

// ---------------- scratch (static, no allocs) ----------------
__device__ float g_y2 [(size_t)N_NODES * 128];
__device__ float g_y34[(size_t)N_NODES * 128];
__device__ __nv_bfloat16 g_Wh[384 * 128];
__device__ __nv_bfloat16 g_Wl[384 * 128];
__device__ float g_bc[384];
// CSR-by-dst build
__device__ int g_cnt[N_NODES];
__device__ int g_off[N_NODES];
__device__ int g_cur[N_NODES];
__device__ int g_bsum[NBLK];
__device__ int g_srcs[N_EDGES];

__device__ __forceinline__ uint32_t smem_u32(const void* p) {
    uint32_t a;
    asm("{ .reg .u64 t; cvta.to.shared.u64 t, %1; cvt.u32.u64 %0, t; }" : "=r"(a) : "l"(p));
    return a;
}
__device__ __forceinline__ void ldm4(uint32_t* r, uint32_t addr) {
    asm volatile("ldmatrix.sync.aligned.m8n8.x4.shared.b16 {%0,%1,%2,%3}, [%4];"
                 : "=r"(r[0]), "=r"(r[1]), "=r"(r[2]), "=r"(r[3]) : "r"(addr));
}
__device__ __forceinline__ void mma_bf16(float* d, const uint32_t* a, const uint32_t* b) {
    asm volatile(
        "mma.sync.aligned.m16n8k16.row.col.f32.bf16.bf16.f32 "
        "{%0,%1,%2,%3}, {%4,%5,%6,%7}, {%8,%9}, {%0,%1,%2,%3};"
        : "+f"(d[0]), "+f"(d[1]), "+f"(d[2]), "+f"(d[3])
        : "r"(a[0]), "r"(a[1]), "r"(a[2]), "r"(a[3]), "r"(b[0]), "r"(b[1]));
}

// ---------------- prep: combined W, bf16 hi/lo split ----------------
__global__ void prep_kernel(const float* __restrict__ W1, const float* __restrict__ b1,
                            const float* __restrict__ W2, const float* __restrict__ b2,
                            const float* __restrict__ W3, const float* __restrict__ b3,
                            const float* __restrict__ W4, const float* __restrict__ b4) {
    int idx = blockIdx.x * blockDim.x + threadIdx.x;
    if (idx < 384 * 128) {
        int r = idx >> 7, c = idx & 127;
        float v;
        if (r < 128)      v = W1[idx];
        else if (r < 256) v = 2.f * W2[(r - 128) * 128 + c];
        else              v = 2.f * (W3[(r - 256) * 128 + c] + W4[(r - 256) * 128 + c]);
        __nv_bfloat16 h = __float2bfloat16(v);
        __nv_bfloat16 l = __float2bfloat16(v - __bfloat162float(h));
        g_Wh[idx] = h;
        g_Wl[idx] = l;
    }
    if (idx < 384) {
        float v;
        if (idx < 128)      v = b1[idx];
        else if (idx < 256) v = 2.f * b2[idx - 128];
        else                v = 2.f * (b3[idx - 256] + b4[idx - 256]);
        g_bc[idx] = v;
    }
}

// ---------------- HMMA bf16x3 GEMM (unchanged from R3) ----------------
#define PITCH_B 272
#define SA_H 0
#define SA_L 34816
#define SB_H 69632
#define SB_L 104448
#define SM_TOT 139264

__global__ void __launch_bounds__(256, 1) gemm_kernel(const float* __restrict__ x,
                                                      float* __restrict__ out) {
    extern __shared__ char smem[];
    const uint32_t sb = smem_u32(smem);
    const int tid = threadIdx.x, lane = tid & 31, wid = tid >> 5;
    const int m0 = blockIdx.x * 128;
    const int wm = wid >> 1, wn = wid & 1;

    for (int i = tid; i < 128 * 64; i += 256) {
        int r = i >> 6, p = i & 63;
        int m = m0 + r;
        float v0 = 0.f, v1 = 0.f;
        if (m < N_NODES) {
            float2 f = ((const float2*)x)[(size_t)m * 64 + p];
            v0 = f.x; v1 = f.y;
        }
        __nv_bfloat16 h0 = __float2bfloat16(v0), h1 = __float2bfloat16(v1);
        __nv_bfloat16 l0 = __float2bfloat16(v0 - __bfloat162float(h0));
        __nv_bfloat16 l1 = __float2bfloat16(v1 - __bfloat162float(h1));
        uint32_t hp = ((uint32_t)__bfloat16_as_ushort(h1) << 16) | __bfloat16_as_ushort(h0);
        uint32_t lp = ((uint32_t)__bfloat16_as_ushort(l1) << 16) | __bfloat16_as_ushort(l0);
        int off = r * PITCH_B + p * 4;
        *(uint32_t*)(smem + SA_H + off) = hp;
        *(uint32_t*)(smem + SA_L + off) = lp;
    }

    const int aOff = ((lane & 7) + ((lane >> 3) & 1) * 8) * PITCH_B + (lane >> 4) * 16;
    const int bOff = ((lane & 7) + ((lane >> 4) & 1) * 8) * PITCH_B + ((lane >> 3) & 1) * 16;
    const int tq = lane >> 2, tr = lane & 3;

    for (int nt = 0; nt < 3; nt++) {
        __syncthreads();
        for (int i = tid; i < 128 * 64; i += 256) {
            int n = i >> 6, p = i & 63;
            uint32_t hp = *(const uint32_t*)(g_Wh + ((size_t)(nt * 128 + n) * 128 + p * 2));
            uint32_t lp = *(const uint32_t*)(g_Wl + ((size_t)(nt * 128 + n) * 128 + p * 2));
            int off = n * PITCH_B + p * 4;
            *(uint32_t*)(smem + SB_H + off) = hp;
            *(uint32_t*)(smem + SB_L + off) = lp;
        }
        __syncthreads();

        float acc[2][8][4];
        #pragma unroll
        for (int mt = 0; mt < 2; mt++)
            #pragma unroll
            for (int nb = 0; nb < 8; nb++)
                #pragma unroll
                for (int j = 0; j < 4; j++) acc[mt][nb][j] = 0.f;

        #pragma unroll
        for (int ks = 0; ks < 8; ks++) {
            const int k0b = ks * 32;
            uint32_t Ah[2][4], Al[2][4];
            #pragma unroll
            for (int mt = 0; mt < 2; mt++) {
                int tb = (wm * 32 + mt * 16) * PITCH_B + k0b;
                ldm4(Ah[mt], sb + SA_H + tb + aOff);
                ldm4(Al[mt], sb + SA_L + tb + aOff);
            }
            uint32_t Bh[16], Bl[16];
            #pragma unroll
            for (int q = 0; q < 4; q++) {
                int tb = (wn * 64 + q * 16) * PITCH_B + k0b;
                ldm4(Bh + q * 4, sb + SB_H + tb + bOff);
                ldm4(Bl + q * 4, sb + SB_L + tb + bOff);
            }
            #pragma unroll
            for (int mt = 0; mt < 2; mt++)
                #pragma unroll
                for (int nb = 0; nb < 8; nb++) {
                    mma_bf16(acc[mt][nb], Ah[mt], Bh + nb * 2);
                    mma_bf16(acc[mt][nb], Ah[mt], Bl + nb * 2);
                    mma_bf16(acc[mt][nb], Al[mt], Bh + nb * 2);
                }
        }

        float* base = (nt == 0) ? out : (nt == 1 ? g_y2 : g_y34);
        #pragma unroll
        for (int nb = 0; nb < 8; nb++) {
            int c = wn * 64 + nb * 8 + tr * 2;
            float bx = __ldg(g_bc + nt * 128 + c);
            float by = __ldg(g_bc + nt * 128 + c + 1);
            #pragma unroll
            for (int mt = 0; mt < 2; mt++) {
                int m = m0 + wm * 32 + mt * 16 + tq;
                if (m < N_NODES) {
                    float2 v = make_float2(acc[mt][nb][0] + bx, acc[mt][nb][1] + by);
                    *(float2*)(base + (size_t)m * 128 + c) = v;
                }
                if (m + 8 < N_NODES) {
                    float2 v = make_float2(acc[mt][nb][2] + bx, acc[mt][nb][3] + by);
                    *(float2*)(base + (size_t)(m + 8) * 128 + c) = v;
                }
            }
        }
    }
}

// ---------------- CSR-by-dst build ----------------
__global__ void zero_cnt_kernel() {
    int i = blockIdx.x * blockDim.x + threadIdx.x;
    if (i < N_NODES) g_cnt[i] = 0;
}
__global__ void hist_kernel(const int* __restrict__ edge) {
    int e = blockIdx.x * blockDim.x + threadIdx.x;
    if (e < N_EDGES) atomicAdd(&g_cnt[__ldg(edge + N_EDGES + e)], 1);
}
__global__ void scan1_kernel() {
    __shared__ int sh[256];
    int tid = threadIdx.x;
    int i = blockIdx.x * 256 + tid;
    int v = (i < N_NODES) ? g_cnt[i] : 0;
    sh[tid] = v;
    __syncthreads();
    for (int o = 1; o < 256; o <<= 1) {
        int t = (tid >= o) ? sh[tid - o] : 0;
        __syncthreads();
        sh[tid] += t;
        __syncthreads();
    }
    if (i < N_NODES) g_off[i] = sh[tid] - v;
    if (tid == 255) g_bsum[blockIdx.x] = sh[255];
}
__global__ void scan2_kernel() {
    __shared__ int sh[512];
    int tid = threadIdx.x;
    int v = (tid < NBLK) ? g_bsum[tid] : 0;
    sh[tid] = v;
    __syncthreads();
    for (int o = 1; o < 512; o <<= 1) {
        int t = (tid >= o) ? sh[tid - o] : 0;
        __syncthreads();
        sh[tid] += t;
        __syncthreads();
    }
    if (tid < NBLK) g_bsum[tid] = sh[tid] - v;
}
__global__ void scan3_kernel() {
    int i = blockIdx.x * blockDim.x + threadIdx.x;
    if (i < N_NODES) {
        int o = g_off[i] + g_bsum[i >> 8];
        g_off[i] = o;
        g_cur[i] = o;
    }
}
__global__ void fill_kernel(const int* __restrict__ edge) {
    int e = blockIdx.x * blockDim.x + threadIdx.x;
    if (e >= N_EDGES) return;
    int src = __ldg(edge + e);
    int dst = __ldg(edge + N_EDGES + e);
    int p = atomicAdd(&g_cur[dst], 1);
    g_srcs[p] = src;
}

// ---------------- fused gather + epilogue: warp per node ----------------
// out = sigmoid(sum y34[srcs]) * sum y2[srcs] + x1   (x1 already in out)
__global__ void __launch_bounds__(256) gather_kernel(float* __restrict__ out) {
    int gid = blockIdx.x * blockDim.x + threadIdx.x;
    int n = gid >> 5, lane = gid & 31;
    if (n >= N_NODES) return;
    int j = __ldg(g_off + n);
    int e = j + __ldg(g_cnt + n);

    float4 a2 = make_float4(0.f, 0.f, 0.f, 0.f);
    float4 a34 = make_float4(0.f, 0.f, 0.f, 0.f);

    for (; j + 1 < e; j += 2) {
        int s0 = __ldg(g_srcs + j);
        int s1 = __ldg(g_srcs + j + 1);
        float4 u2 = __ldg((const float4*)(g_y2 + (size_t)s0 * 128) + lane);
        float4 u34 = __ldg((const float4*)(g_y34 + (size_t)s0 * 128) + lane);
        float4 v2 = __ldg((const float4*)(g_y2 + (size_t)s1 * 128) + lane);
        float4 v34 = __ldg((const float4*)(g_y34 + (size_t)s1 * 128) + lane);
        a2.x += u2.x + v2.x;  a2.y += u2.y + v2.y;
        a2.z += u2.z + v2.z;  a2.w += u2.w + v2.w;
        a34.x += u34.x + v34.x;  a34.y += u34.y + v34.y;
        a34.z += u34.z + v34.z;  a34.w += u34.w + v34.w;
    }
    if (j < e) {
        int s0 = __ldg(g_srcs + j);
        float4 u2 = __ldg((const float4*)(g_y2 + (size_t)s0 * 128) + lane);
        float4 u34 = __ldg((const float4*)(g_y34 + (size_t)s0 * 128) + lane);
        a2.x += u2.x;  a2.y += u2.y;  a2.z += u2.z;  a2.w += u2.w;
        a34.x += u34.x;  a34.y += u34.y;  a34.z += u34.z;  a34.w += u34.w;
    }

    float4* op = (float4*)(out + (size_t)n * 128) + lane;
    float4 x1 = *op;
    float4 r;
    r.x = fmaf(a2.x, __frcp_rn(1.f + __expf(-a34.x)), x1.x);
    r.y = fmaf(a2.y, __frcp_rn(1.f + __expf(-a34.y)), x1.y);
    r.z = fmaf(a2.z, __frcp_rn(1.f + __expf(-a34.z)), x1.z);
    r.w = fmaf(a2.w, __frcp_rn(1.f + __expf(-a34.w)), x1.w);
    *op = r;
}

extern "C" void kernel_launch(void* const* d_in, const int* in_sizes, int n_in,
                              void* d_out, int out_size) {
    const float* x  = (const float*)d_in[0];
    const int* edge = (const int*)d_in[1];
    const float* W1 = (const float*)d_in[2];
    const float* b1 = (const float*)d_in[3];
    const float* W2 = (const float*)d_in[4];
    const float* b2 = (const float*)d_in[5];
    const float* W3 = (const float*)d_in[6];
    const float* b3 = (const float*)d_in[7];
    const float* W4 = (const float*)d_in[8];
    const float* b4 = (const float*)d_in[9];
    float* out = (float*)d_out;

    cudaFuncSetAttribute(gemm_kernel, cudaFuncAttributeMaxDynamicSharedMemorySize, SM_TOT);

    prep_kernel<<<(384 * 128 + 255) / 256, 256>>>(W1, b1, W2, b2, W3, b3, W4, b4);
    zero_cnt_kernel<<<NBLK, 256>>>();
    hist_kernel<<<(N_EDGES + 255) / 256, 256>>>(edge);
    scan1_kernel<<<NBLK, 256>>>();
    scan2_kernel<<<1, 512>>>();
    scan3_kernel<<<NBLK, 256>>>();
    fill_kernel<<<(N_EDGES + 255) / 256, 256>>>(edge);
    gemm_kernel<<<(N_NODES + 127) / 128, 256, SM_TOT>>>(x, out);
    gather_kernel<<<(N_NODES * 32 + 255) / 256, 256>>>(out);
}